// round 1
// baseline (speedup 1.0000x reference)
#include <cuda_runtime.h>
#include <math.h>

// Problem constants
#define Bdim 128
#define NN   1023
#define Xd   256
#define Hd   256
#define KD   512     // H + X
#define GD   1024    // 4 gates * H
#define MAXCNT 256   // max parent count per level (level 8)
#define MAXM   (Bdim*MAXCNT)   // 32768

// Static device scratch (allocation-free rule)
__device__ float g_h[2][Bdim*MAXCNT*Hd];   // ping-pong hidden states per level
__device__ float g_c[2][Bdim*MAXCNT*Hd];   // ping-pong cell states
__device__ float g_hsum[MAXM*KD];          // GEMM A matrix  [M, 512]
__device__ float g_gates[MAXM*GD];         // GEMM C matrix  [M, 1024] (pre-activation + bias)
__device__ float g_leaf_h[Hd];
__device__ float g_leaf_c[Hd];
__device__ float g_bias[GD];               // per-gate combined bias (b? + b_?)
__device__ float g_y[Bdim*Hd];
__device__ float g_t[Bdim*Hd];
__device__ float g_z[Bdim*Hd];

__device__ __forceinline__ float sigmoidf_(float x) { return 1.0f / (1.0f + expf(-x)); }

// ---------------------------------------------------------------------------
// Tiny setup kernel: leaf h/c vectors (constant across batch & leaves) and the
// combined per-gate bias vector used in the GEMM epilogue.
// ---------------------------------------------------------------------------
__global__ void leaf_bias_kernel(const float* __restrict__ bf, const float* __restrict__ b_f,
                                 const float* __restrict__ bi, const float* __restrict__ b_i,
                                 const float* __restrict__ bu, const float* __restrict__ b_u,
                                 const float* __restrict__ bo, const float* __restrict__ b_o) {
    int j = threadIdx.x;  // 256 threads
    float ig = sigmoidf_(bi[j] + b_i[j]);
    float ug = tanhf(bu[j] + b_u[j]);
    float cl = ig * ug;
    g_leaf_c[j] = cl;
    g_leaf_h[j] = sigmoidf_(bo[j] + b_o[j]) * tanhf(cl);
    g_bias[j]       = bf[j] + b_f[j];
    g_bias[256 + j] = bi[j] + b_i[j];
    g_bias[512 + j] = bu[j] + b_u[j];
    g_bias[768 + j] = bo[j] + b_o[j];
}

// ---------------------------------------------------------------------------
// prepare: h_sum[m, :] = [h_c0 + h_c1 (256) | e_c0 + e_c1 (256)]
// Leaf level: h children are the constant leaf vector (x2).
// One float4 per thread.
// ---------------------------------------------------------------------------
__global__ void prepare_kernel(const float* __restrict__ embed, int cnt, int leaf, int child) {
    int idx = blockIdx.x * blockDim.x + threadIdx.x;
    int M = Bdim * cnt;
    if (idx >= M * 128) return;        // 128 float4 per row of 512
    int m = idx >> 7;
    int q = idx & 127;
    int b = m / cnt;
    int n = m - b * cnt;
    float4 v;
    if (q < 64) {
        if (leaf) {
            int j = q * 4;
            v.x = 2.0f * g_leaf_h[j];
            v.y = 2.0f * g_leaf_h[j + 1];
            v.z = 2.0f * g_leaf_h[j + 2];
            v.w = 2.0f * g_leaf_h[j + 3];
        } else {
            const float4* hc = (const float4*)(g_h[child] + (size_t)(b * 2 * cnt + 2 * n) * Hd) + q;
            float4 a = hc[0];
            float4 c = hc[Hd / 4];     // sibling row, H floats later
            v.x = a.x + c.x; v.y = a.y + c.y; v.z = a.z + c.z; v.w = a.w + c.w;
        }
    } else {
        int node0 = 2 * cnt - 1 + 2 * n;  // first child global node index
        const float4* e0 = (const float4*)(embed + ((size_t)b * NN + node0) * Xd) + (q - 64);
        const float4* e1 = (const float4*)(embed + ((size_t)b * NN + node0 + 1) * Xd) + (q - 64);
        float4 a = *e0, c = *e1;
        v.x = a.x + c.x; v.y = a.y + c.y; v.z = a.z + c.z; v.w = a.w + c.w;
    }
    ((float4*)g_hsum)[idx] = v;
}

// ---------------------------------------------------------------------------
// SGEMM: g_gates[M,1024] = g_hsum[M,512] @ W_all^T + bias
// W_all = stack(Wf, Wi, Wu, Wo), each [256, 512] row-major.
// 128x128 block tile, BK=16, 256 threads, 8x8 per thread.
// M is always a multiple of 128, so no guards anywhere.
// ---------------------------------------------------------------------------
__global__ void __launch_bounds__(256) gemm_kernel(const float* __restrict__ Wf,
                                                   const float* __restrict__ Wi,
                                                   const float* __restrict__ Wu,
                                                   const float* __restrict__ Wo) {
    __shared__ float As[16][128];
    __shared__ float Bs[16][128];

    int rowBase = blockIdx.y * 128;
    int colBase = blockIdx.x * 128;
    int gate = colBase >> 8;                       // 128-col tile never straddles a gate
    const float* W = (gate == 0) ? Wf : (gate == 1) ? Wi : (gate == 2) ? Wu : Wo;
    int wcol = colBase & 255;

    int t  = threadIdx.x;
    int tx = t & 15, ty = t >> 4;
    int lr = t >> 1;            // 0..127: tile row (A) / tile col (B)
    int lf = (t & 1) * 2;       // float4 pair offset: 0 or 2
    int kb = lf * 4;            // k offset in smem: 0 or 8

    float acc[8][8];
#pragma unroll
    for (int i = 0; i < 8; i++)
#pragma unroll
        for (int j = 0; j < 8; j++) acc[i][j] = 0.0f;

    const float4* Ag = (const float4*)(g_hsum + (size_t)(rowBase + lr) * KD) + lf;
    const float4* Bg = (const float4*)(W + (size_t)(wcol + lr) * KD) + lf;

    for (int k0 = 0; k0 < KD; k0 += 16) {
        float4 a0 = Ag[0], a1 = Ag[1];
        float4 b0 = Bg[0], b1 = Bg[1];
        Ag += 4; Bg += 4;

        As[kb + 0][lr] = a0.x; As[kb + 1][lr] = a0.y; As[kb + 2][lr] = a0.z; As[kb + 3][lr] = a0.w;
        As[kb + 4][lr] = a1.x; As[kb + 5][lr] = a1.y; As[kb + 6][lr] = a1.z; As[kb + 7][lr] = a1.w;
        Bs[kb + 0][lr] = b0.x; Bs[kb + 1][lr] = b0.y; Bs[kb + 2][lr] = b0.z; Bs[kb + 3][lr] = b0.w;
        Bs[kb + 4][lr] = b1.x; Bs[kb + 5][lr] = b1.y; Bs[kb + 6][lr] = b1.z; Bs[kb + 7][lr] = b1.w;
        __syncthreads();

#pragma unroll
        for (int k = 0; k < 16; k++) {
            float av[8], bv[8];
#pragma unroll
            for (int i = 0; i < 8; i++) av[i] = As[k][ty * 8 + i];
#pragma unroll
            for (int j = 0; j < 8; j++) bv[j] = Bs[k][tx * 8 + j];
#pragma unroll
            for (int i = 0; i < 8; i++)
#pragma unroll
                for (int j = 0; j < 8; j++) acc[i][j] += av[i] * bv[j];
        }
        __syncthreads();
    }

    float4 bs0 = *(const float4*)(g_bias + colBase + tx * 8);
    float4 bs1 = *(const float4*)(g_bias + colBase + tx * 8 + 4);
#pragma unroll
    for (int i = 0; i < 8; i++) {
        float* cp = g_gates + (size_t)(rowBase + ty * 8 + i) * GD + colBase + tx * 8;
        float4 v0 = make_float4(acc[i][0] + bs0.x, acc[i][1] + bs0.y,
                                acc[i][2] + bs0.z, acc[i][3] + bs0.w);
        float4 v1 = make_float4(acc[i][4] + bs1.x, acc[i][5] + bs1.y,
                                acc[i][6] + bs1.z, acc[i][7] + bs1.w);
        *(float4*)cp       = v0;
        *(float4*)(cp + 4) = v1;
    }
}

// ---------------------------------------------------------------------------
// gates -> (h_new, c_new) for the parent level.
// ---------------------------------------------------------------------------
__global__ void gate_kernel(int cnt, int leaf, int child, int parent) {
    int idx = blockIdx.x * blockDim.x + threadIdx.x;
    int M = Bdim * cnt;
    if (idx >= M * Hd) return;
    int m = idx >> 8;
    int j = idx & 255;
    const float* gr = g_gates + (size_t)m * GD;
    float f = sigmoidf_(gr[j]);
    float i = sigmoidf_(gr[256 + j]);
    float u = tanhf(gr[512 + j]);
    float o = sigmoidf_(gr[768 + j]);
    float csum;
    if (leaf) {
        csum = 2.0f * g_leaf_c[j];
    } else {
        int b = m / cnt;
        int n = m - b * cnt;
        const float* cc = g_c[child] + (size_t)(b * 2 * cnt + 2 * n) * Hd + j;
        csum = cc[0] + cc[Hd];
    }
    float cn = i * u + f * csum;
    g_c[parent][idx] = cn;
    g_h[parent][idx] = o * tanhf(cn);
}

// ---------------------------------------------------------------------------
// Head MLP: out = act(A @ W^T + bias [+ g_y]).
// src: 0 -> g_h[1] (tree root), 1 -> g_t, 2 -> g_z
// dst: 0 -> g_y, 1 -> g_t, 2 -> g_z, 3 -> final out
// act: 0 none, 1 tanh, 2 relu
// Tiny GEMMs (128x256x256): one block per batch row.
// ---------------------------------------------------------------------------
__global__ void head_kernel(const float* __restrict__ W, const float* __restrict__ bias,
                            int src, int dst, int addy, int act, float* __restrict__ out) {
    __shared__ float arow[256];
    int b = blockIdx.x;
    int j = threadIdx.x;
    const float* A = (src == 0) ? g_h[1] : (src == 1) ? g_t : g_z;
    arow[j] = A[b * 256 + j];
    __syncthreads();
    float acc = bias[j];
    const float* wr = W + j * 256;
#pragma unroll 8
    for (int k = 0; k < 256; k++) acc += arow[k] * wr[k];
    if (addy) acc += g_y[b * 256 + j];
    if (act == 1) acc = tanhf(acc);
    else if (act == 2) acc = fmaxf(acc, 0.0f);
    float* O = (dst == 0) ? g_y : (dst == 1) ? g_t : (dst == 2) ? g_z : out;
    O[b * 256 + j] = acc;
}

// ---------------------------------------------------------------------------
extern "C" void kernel_launch(void* const* d_in, const int* in_sizes, int n_in,
                              void* d_out, int out_size) {
    const float* embed = (const float*)d_in[0];
    const float* Wf  = (const float*)d_in[1];
    const float* bf  = (const float*)d_in[2];
    const float* b_f = (const float*)d_in[3];
    const float* Wi  = (const float*)d_in[4];
    const float* bi  = (const float*)d_in[5];
    const float* b_i = (const float*)d_in[6];
    const float* Wu  = (const float*)d_in[7];
    const float* bu  = (const float*)d_in[8];
    const float* b_u = (const float*)d_in[9];
    const float* Wo  = (const float*)d_in[10];
    const float* bo  = (const float*)d_in[11];
    const float* b_o = (const float*)d_in[12];
    const float* W1  = (const float*)d_in[13];
    const float* bl1 = (const float*)d_in[14];
    const float* W2  = (const float*)d_in[15];
    const float* bl2 = (const float*)d_in[16];
    const float* W3  = (const float*)d_in[17];
    const float* bl3 = (const float*)d_in[18];
    const float* W4  = (const float*)d_in[19];
    const float* bl4 = (const float*)d_in[20];
    float* out = (float*)d_out;

    leaf_bias_kernel<<<1, 256>>>(bf, b_f, bi, b_i, bu, b_u, bo, b_o);

    int pp = 0;
    for (int l = 8; l >= 0; --l) {
        int cnt = 1 << l;
        int M = Bdim * cnt;
        int leaf = (l == 8);
        int child = pp, parent = pp ^ 1;
        prepare_kernel<<<(M * 128 + 255) / 256, 256>>>(embed, cnt, leaf, child);
        gemm_kernel<<<dim3(8, M / 128), 256>>>(Wf, Wi, Wu, Wo);
        gate_kernel<<<(M * 256 + 255) / 256, 256>>>(cnt, leaf, child, parent);
        pp = parent;
    }
    // After 9 levels pp == 1: root hidden state lives in g_h[1][0 : 128*256].

    head_kernel<<<128, 256>>>(W1, bl1, 0, 0, 0, 1, out);  // y  = tanh(hr @ W1^T + bl1)
    head_kernel<<<128, 256>>>(W2, bl2, 0, 1, 0, 2, out);  // t  = relu(hr @ W2^T + bl2)
    head_kernel<<<128, 256>>>(W3, bl3, 1, 2, 1, 0, out);  // z  = t @ W3^T + bl3 + y
    head_kernel<<<128, 256>>>(W4, bl4, 2, 3, 0, 2, out);  // out = relu(z @ W4^T + bl4)
}

// round 3
// speedup vs baseline: 2.1530x; 2.1530x over previous
#include <cuda_runtime.h>
#include <cuda_bf16.h>
#include <math.h>
#include <stdint.h>

// Problem constants
#define Bdim 128
#define NN   1023
#define Xd   256
#define Hd   256
#define KD   512     // H + X
#define GD   1024    // 4 gates * H
#define MAXCNT 256
#define MAXM   (Bdim*MAXCNT)   // 32768

// ---------------------------------------------------------------------------
// Static device scratch (allocation-free rule)
// ---------------------------------------------------------------------------
__device__ float g_h[2][MAXM*Hd];            // ping-pong hidden states
__device__ float g_c[2][MAXM*Hd];            // ping-pong cell states
__device__ __nv_bfloat16 g_ahi[MAXM*KD];     // A (h_sum) bf16 high part
__device__ __nv_bfloat16 g_alo[MAXM*KD];     // A bf16 low part
__device__ __nv_bfloat16 g_whi[GD*KD];       // W interleaved (row = j*4+gate), hi
__device__ __nv_bfloat16 g_wlo[GD*KD];       // lo
__device__ float g_leaf_h[Hd];
__device__ float g_leaf_c[Hd];
__device__ float g_bias[GD];                 // gate-major: [f(256) i(256) u(256) o(256)]
__device__ float g_y[Bdim*Hd];
__device__ float g_t[Bdim*Hd];
__device__ float g_z[Bdim*Hd];

__device__ __forceinline__ float sigmoidf_(float x) { return 1.0f / (1.0f + expf(-x)); }

__device__ __forceinline__ uint32_t smem_to_u32(const void* p) {
    uint32_t a;
    asm("{ .reg .u64 t; cvta.to.shared.u64 t, %1; cvt.u32.u64 %0, t; }" : "=r"(a) : "l"(p));
    return a;
}
__device__ __forceinline__ uint32_t lds_u32(uint32_t addr) {
    uint32_t v;
    asm volatile("ld.shared.b32 %0, [%1];" : "=r"(v) : "r"(addr));
    return v;
}
#define CP_ASYNC16(daddr, src) \
    asm volatile("cp.async.cg.shared.global [%0], [%1], 16;" :: "r"(daddr), "l"(src) : "memory")
#define CP_COMMIT() asm volatile("cp.async.commit_group;" ::: "memory")
#define CP_WAIT(n)  asm volatile("cp.async.wait_group %0;" :: "n"(n) : "memory")

#define MMA_BF16(d, a0, a1, a2, a3, b0, b1) \
    asm volatile("mma.sync.aligned.m16n8k16.row.col.f32.bf16.bf16.f32 " \
        "{%0,%1,%2,%3}, {%4,%5,%6,%7}, {%8,%9}, {%0,%1,%2,%3};" \
        : "+f"((d)[0]), "+f"((d)[1]), "+f"((d)[2]), "+f"((d)[3]) \
        : "r"(a0), "r"(a1), "r"(a2), "r"(a3), "r"(b0), "r"(b1))

// GEMM kernel geometry
#define GT 128                    // threads (4 warps)
#define K_CHUNK 32
#define NCHUNK  (KD / K_CHUNK)    // 16
// smem stage layout (rows of 32 bf16 = 64B, XOR-swizzled at 16B granularity)
#define AHI_OFF 0                 // 64 rows  * 64B = 4096
#define ALO_OFF 4096
#define BHI_OFF 8192              // 256 rows * 64B = 16384
#define BLO_OFF 24576
#define STAGE_BYTES 40960
#define SMEM_SZ (2 * STAGE_BYTES) // 81920

// phys addr of byte kb (0..63) within swizzled 64B row
__device__ __forceinline__ uint32_t swz_addr(uint32_t base, int row, int kb) {
    return base + row * 64 + (((((uint32_t)kb >> 4) ^ ((uint32_t)row >> 1)) & 3u) << 4) + (kb & 15);
}

// ---------------------------------------------------------------------------
// Setup: leaf vectors + gate-major combined bias
// ---------------------------------------------------------------------------
__global__ void leaf_bias_kernel(const float* __restrict__ bf, const float* __restrict__ b_f,
                                 const float* __restrict__ bi, const float* __restrict__ b_i,
                                 const float* __restrict__ bu, const float* __restrict__ b_u,
                                 const float* __restrict__ bo, const float* __restrict__ b_o) {
    int j = threadIdx.x;
    float ig = sigmoidf_(bi[j] + b_i[j]);
    float ug = tanhf(bu[j] + b_u[j]);
    float cl = ig * ug;
    g_leaf_c[j] = cl;
    g_leaf_h[j] = sigmoidf_(bo[j] + b_o[j]) * tanhf(cl);
    g_bias[j]       = bf[j] + b_f[j];
    g_bias[256 + j] = bi[j] + b_i[j];
    g_bias[512 + j] = bu[j] + b_u[j];
    g_bias[768 + j] = bo[j] + b_o[j];
}

// ---------------------------------------------------------------------------
// Weight conversion: interleaved row r = j*4 + gate, bf16 hi/lo split
// ---------------------------------------------------------------------------
__global__ void convert_w_kernel(const float* __restrict__ Wf, const float* __restrict__ Wi,
                                 const float* __restrict__ Wu, const float* __restrict__ Wo) {
    int idx = blockIdx.x * 256 + threadIdx.x;     // 0 .. 1024*512-1
    int r = idx >> 9, k = idx & 511;
    int j = r >> 2, g = r & 3;
    const float* W = (g == 0) ? Wf : (g == 1) ? Wi : (g == 2) ? Wu : Wo;
    float x = W[(size_t)j * 512 + k];
    __nv_bfloat16 hi = __float2bfloat16(x);
    g_whi[idx] = hi;
    g_wlo[idx] = __float2bfloat16(x - __bfloat162float(hi));
}

// ---------------------------------------------------------------------------
// prepare: A[m,:] = [h_c0+h_c1 | e_c0+e_c1] as bf16 hi/lo split
// ---------------------------------------------------------------------------
__global__ void prepare_kernel(const float* __restrict__ embed, int cnt, int leaf, int child) {
    int idx = blockIdx.x * blockDim.x + threadIdx.x;
    int M = Bdim * cnt;
    if (idx >= M * 128) return;
    int m = idx >> 7, q = idx & 127;
    int b = m / cnt, n = m - b * cnt;
    float4 v;
    if (q < 64) {
        if (leaf) {
            int j = q * 4;
            v.x = 2.0f * g_leaf_h[j];
            v.y = 2.0f * g_leaf_h[j + 1];
            v.z = 2.0f * g_leaf_h[j + 2];
            v.w = 2.0f * g_leaf_h[j + 3];
        } else {
            const float4* hc = (const float4*)(g_h[child] + (size_t)(b * 2 * cnt + 2 * n) * Hd) + q;
            float4 a = hc[0];
            float4 c = hc[Hd / 4];
            v.x = a.x + c.x; v.y = a.y + c.y; v.z = a.z + c.z; v.w = a.w + c.w;
        }
    } else {
        int node0 = 2 * cnt - 1 + 2 * n;
        const float4* e0 = (const float4*)(embed + ((size_t)b * NN + node0) * Xd) + (q - 64);
        const float4* e1 = (const float4*)(embed + ((size_t)b * NN + node0 + 1) * Xd) + (q - 64);
        float4 a = *e0, c = *e1;
        v.x = a.x + c.x; v.y = a.y + c.y; v.z = a.z + c.z; v.w = a.w + c.w;
    }
    __nv_bfloat162 h01 = __floats2bfloat162_rn(v.x, v.y);
    __nv_bfloat162 h23 = __floats2bfloat162_rn(v.z, v.w);
    __nv_bfloat162 l01 = __floats2bfloat162_rn(v.x - __bfloat162float(h01.x),
                                               v.y - __bfloat162float(h01.y));
    __nv_bfloat162 l23 = __floats2bfloat162_rn(v.z - __bfloat162float(h23.x),
                                               v.w - __bfloat162float(h23.y));
    ((__nv_bfloat162*)g_ahi)[idx * 2]     = h01;
    ((__nv_bfloat162*)g_ahi)[idx * 2 + 1] = h23;
    ((__nv_bfloat162*)g_alo)[idx * 2]     = l01;
    ((__nv_bfloat162*)g_alo)[idx * 2 + 1] = l23;
}

// ---------------------------------------------------------------------------
// HMMA GEMM + fused gate epilogue.
// CTA: 64 rows x 256 interleaved gate-cols (n = j*4 + gate), K=512 in 16
// chunks of 32, cp.async double buffer, split bf16 (3 MMAs per frag pair).
// Each warp: 16 rows x 256 cols -> 32 n-tiles, acc[32][4].
// Epilogue: shfl_xor(1) pairs (f,i)<->(u,o), gate math in registers,
// h/c written straight to global.
// ---------------------------------------------------------------------------
__global__ void __launch_bounds__(GT) gemm_hmma_kernel(int cnt, int leaf, int child, int parent) {
    extern __shared__ char sm[];
    const uint32_t sb = smem_to_u32(sm);
    const int tid = threadIdx.x;
    const int wid = tid >> 5, lid = tid & 31;
    const int g = lid >> 2, q = lid & 3;
    const int rowBase = blockIdx.y * 64;
    const int colBase = blockIdx.x * 256;   // interleaved n space

    float acc[32][4];
#pragma unroll
    for (int i = 0; i < 32; i++)
#pragma unroll
        for (int k = 0; k < 4; k++) acc[i][k] = 0.0f;

#define LOAD_CHUNK(ch, stg) do {                                                  \
    uint32_t sb_ = sb + (stg) * STAGE_BYTES;                                      \
    _Pragma("unroll")                                                             \
    for (int i = tid; i < 512; i += GT) {                                         \
        int part = i >> 8, r = (i >> 2) & 63, s = i & 3;                          \
        uint32_t d = swz_addr(sb_ + (part ? ALO_OFF : AHI_OFF), r, s * 16);       \
        const __nv_bfloat16* srcp = (part ? g_alo : g_ahi)                        \
            + (size_t)(rowBase + r) * KD + (ch) * K_CHUNK + s * 8;                \
        CP_ASYNC16(d, srcp);                                                      \
    }                                                                             \
    _Pragma("unroll")                                                             \
    for (int i = tid; i < 2048; i += GT) {                                        \
        int part = i >> 10, n = (i >> 2) & 255, s = i & 3;                        \
        uint32_t d = swz_addr(sb_ + (part ? BLO_OFF : BHI_OFF), n, s * 16);       \
        const __nv_bfloat16* srcp = (part ? g_wlo : g_whi)                        \
            + (size_t)(colBase + n) * KD + (ch) * K_CHUNK + s * 8;                \
        CP_ASYNC16(d, srcp);                                                      \
    }                                                                             \
    CP_COMMIT();                                                                  \
} while (0)

    LOAD_CHUNK(0, 0);

    for (int ch = 0; ch < NCHUNK; ch++) {
        int stg = ch & 1;
        if (ch + 1 < NCHUNK) {
            LOAD_CHUNK(ch + 1, stg ^ 1);
            CP_WAIT(1);
        } else {
            CP_WAIT(0);
        }
        __syncthreads();

        uint32_t st = sb + stg * STAGE_BYTES;
        int rowA = wid * 16 + g;
#pragma unroll
        for (int ks = 0; ks < 2; ks++) {
            int kb = ks * 32 + q * 4;     // byte offset of this thread's k pair
            uint32_t ah0 = lds_u32(swz_addr(st + AHI_OFF, rowA,     kb));
            uint32_t ah1 = lds_u32(swz_addr(st + AHI_OFF, rowA + 8, kb));
            uint32_t ah2 = lds_u32(swz_addr(st + AHI_OFF, rowA,     kb + 16));
            uint32_t ah3 = lds_u32(swz_addr(st + AHI_OFF, rowA + 8, kb + 16));
            uint32_t al0 = lds_u32(swz_addr(st + ALO_OFF, rowA,     kb));
            uint32_t al1 = lds_u32(swz_addr(st + ALO_OFF, rowA + 8, kb));
            uint32_t al2 = lds_u32(swz_addr(st + ALO_OFF, rowA,     kb + 16));
            uint32_t al3 = lds_u32(swz_addr(st + ALO_OFF, rowA + 8, kb + 16));
#pragma unroll
            for (int nt = 0; nt < 32; nt++) {
                int rowB = nt * 8 + g;
                uint32_t bh0 = lds_u32(swz_addr(st + BHI_OFF, rowB, kb));
                uint32_t bh1 = lds_u32(swz_addr(st + BHI_OFF, rowB, kb + 16));
                uint32_t bl0 = lds_u32(swz_addr(st + BLO_OFF, rowB, kb));
                uint32_t bl1 = lds_u32(swz_addr(st + BLO_OFF, rowB, kb + 16));
                MMA_BF16(acc[nt], ah0, ah1, ah2, ah3, bh0, bh1);
                MMA_BF16(acc[nt], ah0, ah1, ah2, ah3, bl0, bl1);
                MMA_BF16(acc[nt], al0, al1, al2, al3, bh0, bh1);
            }
        }
        __syncthreads();
    }
#undef LOAD_CHUNK

    // Fused gate epilogue.
    // even q: owns (f,i) at row g       ; gets (u,o) row g   from partner c0,c1
    // odd  q: owns (u,o) at row g+8     ; gets (f,i) row g+8 from partner c2,c3
    const bool evenq = ((q & 1) == 0);
    const int m = rowBase + wid * 16 + g + ((lid & 1) ? 8 : 0);
    const int b = m / cnt, n = m - b * cnt;
    const float* crow = g_c[child] + (size_t)(b * 2 * cnt + 2 * n) * Hd;
    float* hp = g_h[parent] + (size_t)m * Hd;
    float* cp = g_c[parent] + (size_t)m * Hd;
#pragma unroll
    for (int nt = 0; nt < 32; nt++) {
        float t0 = __shfl_xor_sync(0xffffffffu, acc[nt][0], 1);
        float t1 = __shfl_xor_sync(0xffffffffu, acc[nt][1], 1);
        float t2 = __shfl_xor_sync(0xffffffffu, acc[nt][2], 1);
        float t3 = __shfl_xor_sync(0xffffffffu, acc[nt][3], 1);
        float pf = evenq ? acc[nt][0] : t2;
        float pi = evenq ? acc[nt][1] : t3;
        float pu = evenq ? t0 : acc[nt][2];
        float po = evenq ? t1 : acc[nt][3];
        int j = (colBase >> 2) + nt * 2 + (q >> 1);
        float f  = sigmoidf_(pf + g_bias[j]);
        float ig = sigmoidf_(pi + g_bias[256 + j]);
        float u  = tanhf    (pu + g_bias[512 + j]);
        float o  = sigmoidf_(po + g_bias[768 + j]);
        float csum = leaf ? 2.0f * g_leaf_c[j] : (crow[j] + crow[Hd + j]);
        float cn = ig * u + f * csum;
        cp[j] = cn;
        hp[j] = o * tanhf(cn);
    }
}

// ---------------------------------------------------------------------------
// Head MLP (tiny, fp32): out = act(A @ W^T + bias [+ g_y])
// ---------------------------------------------------------------------------
__global__ void head_kernel(const float* __restrict__ W, const float* __restrict__ bias,
                            int src, int dst, int addy, int act, float* __restrict__ out) {
    __shared__ float arow[256];
    int b = blockIdx.x;
    int j = threadIdx.x;
    const float* A = (src == 0) ? g_h[1] : (src == 1) ? g_t : g_z;
    arow[j] = A[b * 256 + j];
    __syncthreads();
    float acc = bias[j];
    const float* wr = W + j * 256;
#pragma unroll 8
    for (int k = 0; k < 256; k++) acc += arow[k] * wr[k];
    if (addy) acc += g_y[b * 256 + j];
    if (act == 1) acc = tanhf(acc);
    else if (act == 2) acc = fmaxf(acc, 0.0f);
    float* O = (dst == 0) ? g_y : (dst == 1) ? g_t : (dst == 2) ? g_z : out;
    O[b * 256 + j] = acc;
}

// ---------------------------------------------------------------------------
extern "C" void kernel_launch(void* const* d_in, const int* in_sizes, int n_in,
                              void* d_out, int out_size) {
    const float* embed = (const float*)d_in[0];
    const float* Wf  = (const float*)d_in[1];
    const float* bf  = (const float*)d_in[2];
    const float* b_f = (const float*)d_in[3];
    const float* Wi  = (const float*)d_in[4];
    const float* bi  = (const float*)d_in[5];
    const float* b_i = (const float*)d_in[6];
    const float* Wu  = (const float*)d_in[7];
    const float* bu  = (const float*)d_in[8];
    const float* b_u = (const float*)d_in[9];
    const float* Wo  = (const float*)d_in[10];
    const float* bo  = (const float*)d_in[11];
    const float* b_o = (const float*)d_in[12];
    const float* W1  = (const float*)d_in[13];
    const float* bl1 = (const float*)d_in[14];
    const float* W2  = (const float*)d_in[15];
    const float* bl2 = (const float*)d_in[16];
    const float* W3  = (const float*)d_in[17];
    const float* bl3 = (const float*)d_in[18];
    const float* W4  = (const float*)d_in[19];
    const float* bl4 = (const float*)d_in[20];
    float* out = (float*)d_out;

    cudaFuncSetAttribute(gemm_hmma_kernel, cudaFuncAttributeMaxDynamicSharedMemorySize, SMEM_SZ);

    leaf_bias_kernel<<<1, 256>>>(bf, b_f, bi, b_i, bu, b_u, bo, b_o);
    convert_w_kernel<<<2048, 256>>>(Wf, Wi, Wu, Wo);

    int pp = 0;
    for (int l = 8; l >= 0; --l) {
        int cnt = 1 << l;
        int M = Bdim * cnt;
        int leaf = (l == 8);
        int child = pp, parent = pp ^ 1;
        prepare_kernel<<<(M * 128 + 255) / 256, 256>>>(embed, cnt, leaf, child);
        gemm_hmma_kernel<<<dim3(4, M / 64), GT, SMEM_SZ>>>(cnt, leaf, child, parent);
        pp = parent;
    }
    // pp == 1: root hidden state in g_h[1][0 : 128*256]

    head_kernel<<<128, 256>>>(W1, bl1, 0, 0, 0, 1, out);  // y  = tanh(hr @ W1^T + bl1)
    head_kernel<<<128, 256>>>(W2, bl2, 0, 1, 0, 2, out);  // t  = relu(hr @ W2^T + bl2)
    head_kernel<<<128, 256>>>(W3, bl3, 1, 2, 1, 0, out);  // z  = t @ W3^T + bl3 + y
    head_kernel<<<128, 256>>>(W4, bl4, 2, 3, 0, 2, out);  // out = relu(z @ W4^T + bl4)
}

// round 4
// speedup vs baseline: 2.8558x; 1.3264x over previous
#include <cuda_runtime.h>
#include <cuda_bf16.h>
#include <math.h>
#include <stdint.h>

// Problem constants
#define Bdim 128
#define NN   1023
#define Xd   256
#define Hd   256
#define KD   512     // H + X
#define GD   1024    // 4 gates * H
#define MAXCNT 256
#define MAXM   (Bdim*MAXCNT)   // 32768

// ---------------------------------------------------------------------------
// Static device scratch (allocation-free rule)
// ---------------------------------------------------------------------------
__device__ float g_h[2][MAXM*Hd];            // ping-pong hidden states
__device__ float g_c[2][MAXM*Hd];            // ping-pong cell states
__device__ __nv_bfloat16 g_ahi[MAXM*KD];     // A (h_sum) bf16 high part
__device__ __nv_bfloat16 g_alo[MAXM*KD];     // A bf16 low part
// W packed in mma-fragment order: [colblk 8][chunk 16][ks 2][nt 16][lane 32]
// each uint4 = {bh0, bh1, bl0, bl1} for that lane's m16n8k16 B fragment.
__device__ uint4 g_wpack[8*16*2*16*32];      // 131072 * 16B = 2 MB
__device__ float g_leaf_h[Hd];
__device__ float g_leaf_c[Hd];
__device__ float g_bias[GD];                 // gate-major: [f(256) i(256) u(256) o(256)]
__device__ float g_biasleaf[GD];             // g_bias + leaf-h constant dot (gate-major)
__device__ float g_y[Bdim*Hd];
__device__ float g_t[Bdim*Hd];
__device__ float g_z[Bdim*Hd];

__device__ __forceinline__ float sigmoidf_(float x) { return 1.0f / (1.0f + expf(-x)); }

__device__ __forceinline__ uint32_t smem_to_u32(const void* p) {
    uint32_t a;
    asm("{ .reg .u64 t; cvta.to.shared.u64 t, %1; cvt.u32.u64 %0, t; }" : "=r"(a) : "l"(p));
    return a;
}
__device__ __forceinline__ uint32_t lds_u32(uint32_t addr) {
    uint32_t v;
    asm volatile("ld.shared.b32 %0, [%1];" : "=r"(v) : "r"(addr));
    return v;
}
__device__ __forceinline__ uint4 lds_u128(uint32_t addr) {
    uint4 v;
    asm volatile("ld.shared.v4.b32 {%0,%1,%2,%3}, [%4];"
                 : "=r"(v.x), "=r"(v.y), "=r"(v.z), "=r"(v.w) : "r"(addr));
    return v;
}
#define CP_ASYNC16(daddr, src) \
    asm volatile("cp.async.cg.shared.global [%0], [%1], 16;" :: "r"(daddr), "l"(src) : "memory")
#define CP_COMMIT() asm volatile("cp.async.commit_group;" ::: "memory")
#define CP_WAIT(n)  asm volatile("cp.async.wait_group %0;" :: "n"(n) : "memory")

#define MMA_BF16(d, a0, a1, a2, a3, b0, b1) \
    asm volatile("mma.sync.aligned.m16n8k16.row.col.f32.bf16.bf16.f32 " \
        "{%0,%1,%2,%3}, {%4,%5,%6,%7}, {%8,%9}, {%0,%1,%2,%3};" \
        : "+f"((d)[0]), "+f"((d)[1]), "+f"((d)[2]), "+f"((d)[3]) \
        : "r"(a0), "r"(a1), "r"(a2), "r"(a3), "r"(b0), "r"(b1))

// GEMM geometry: CTA = 64 rows x 128 interleaved cols, 128 threads (4 warps)
#define GT 128
#define K_CHUNK 32
// smem stage layout
#define AHI_OFF 0                 // 64 rows * 64B = 4096
#define ALO_OFF 4096
#define BPK_OFF 8192              // packed B: 2ks*16nt*32lane*16B = 16384
#define STAGE_BYTES 24576
#define SMEM_SZ (2 * STAGE_BYTES) // 49152

// phys addr of byte kb (0..63) within swizzled 64B A row
__device__ __forceinline__ uint32_t swz_addr(uint32_t base, int row, int kb) {
    return base + row * 64 + (((((uint32_t)kb >> 4) ^ ((uint32_t)row >> 1)) & 3u) << 4) + (kb & 15);
}

__device__ __forceinline__ uint32_t pk_hi(float a, float b) {
    __nv_bfloat162 t = __floats2bfloat162_rn(a, b);
    return *reinterpret_cast<uint32_t*>(&t);
}

// ---------------------------------------------------------------------------
// Setup: leaf vectors + gate-major combined bias
// ---------------------------------------------------------------------------
__global__ void leaf_bias_kernel(const float* __restrict__ bf, const float* __restrict__ b_f,
                                 const float* __restrict__ bi, const float* __restrict__ b_i,
                                 const float* __restrict__ bu, const float* __restrict__ b_u,
                                 const float* __restrict__ bo, const float* __restrict__ b_o) {
    int j = threadIdx.x;
    float ig = sigmoidf_(bi[j] + b_i[j]);
    float ug = tanhf(bu[j] + b_u[j]);
    float cl = ig * ug;
    g_leaf_c[j] = cl;
    g_leaf_h[j] = sigmoidf_(bo[j] + b_o[j]) * tanhf(cl);
    g_bias[j]       = bf[j] + b_f[j];
    g_bias[256 + j] = bi[j] + b_i[j];
    g_bias[512 + j] = bu[j] + b_u[j];
    g_bias[768 + j] = bo[j] + b_o[j];
}

// ---------------------------------------------------------------------------
// Leaf bias fold: g_biasleaf[gate*256+j] = g_bias[...] + sum_{k<256} 2*leaf_h[k]*W[j][k]
// (fp32 exact; lets the leaf GEMM skip the constant h-half of K)
// ---------------------------------------------------------------------------
__global__ void leafdot_kernel(const float* __restrict__ Wf, const float* __restrict__ Wi,
                               const float* __restrict__ Wu, const float* __restrict__ Wo) {
    __shared__ float lh[256];
    int t = threadIdx.x;
    lh[t] = 2.0f * g_leaf_h[t];
    __syncthreads();
    int n = blockIdx.x * 256 + t;     // 0..1023, interleaved n = j*4+gate
    int j = n >> 2, gate = n & 3;
    const float* W = (gate == 0) ? Wf : (gate == 1) ? Wi : (gate == 2) ? Wu : Wo;
    const float* wr = W + (size_t)j * 512;
    float acc = 0.0f;
#pragma unroll 8
    for (int k = 0; k < 256; k++) acc += wr[k] * lh[k];
    g_biasleaf[gate * 256 + j] = g_bias[gate * 256 + j] + acc;
}

// ---------------------------------------------------------------------------
// Weight conversion into packed fragment order (one-time).
// ---------------------------------------------------------------------------
__global__ void convert_w_kernel(const float* __restrict__ Wf, const float* __restrict__ Wi,
                                 const float* __restrict__ Wu, const float* __restrict__ Wo) {
    int idx = blockIdx.x * 256 + threadIdx.x;   // 0 .. 131071
    int lane = idx & 31;
    int nt   = (idx >> 5) & 15;
    int ks   = (idx >> 9) & 1;
    int ch   = (idx >> 10) & 15;
    int cb   = idx >> 14;
    int n = cb * 128 + nt * 8 + (lane >> 2);    // interleaved n = j*4+gate
    int j = n >> 2, gate = n & 3, tig = lane & 3;
    int k0 = ch * 32 + ks * 16 + tig * 2;
    const float* W = (gate == 0) ? Wf : (gate == 1) ? Wi : (gate == 2) ? Wu : Wo;
    const float* wr = W + (size_t)j * 512;
    float w0 = wr[k0], w1 = wr[k0 + 1], w2 = wr[k0 + 8], w3 = wr[k0 + 9];
    float h0 = __bfloat162float(__float2bfloat16(w0));
    float h1 = __bfloat162float(__float2bfloat16(w1));
    float h2 = __bfloat162float(__float2bfloat16(w2));
    float h3 = __bfloat162float(__float2bfloat16(w3));
    uint4 v;
    v.x = pk_hi(w0, w1);            // bh0
    v.y = pk_hi(w2, w3);            // bh1
    v.z = pk_hi(w0 - h0, w1 - h1);  // bl0
    v.w = pk_hi(w2 - h2, w3 - h3);  // bl1
    g_wpack[idx] = v;
}

// ---------------------------------------------------------------------------
// prepare (non-leaf): A[m,:] = [h_c0+h_c1 | e_c0+e_c1] as bf16 hi/lo split
// ---------------------------------------------------------------------------
__global__ void prepare_kernel(const float* __restrict__ embed, int cnt, int child) {
    int idx = blockIdx.x * blockDim.x + threadIdx.x;
    int M = Bdim * cnt;
    if (idx >= M * 128) return;
    int m = idx >> 7, q = idx & 127;
    int b = m / cnt, n = m - b * cnt;
    float4 v;
    if (q < 64) {
        const float4* hc = (const float4*)(g_h[child] + (size_t)(b * 2 * cnt + 2 * n) * Hd) + q;
        float4 a = hc[0];
        float4 c = hc[Hd / 4];
        v.x = a.x + c.x; v.y = a.y + c.y; v.z = a.z + c.z; v.w = a.w + c.w;
    } else {
        int node0 = 2 * cnt - 1 + 2 * n;
        const float4* e0 = (const float4*)(embed + ((size_t)b * NN + node0) * Xd) + (q - 64);
        const float4* e1 = (const float4*)(embed + ((size_t)b * NN + node0 + 1) * Xd) + (q - 64);
        float4 a = *e0, c = *e1;
        v.x = a.x + c.x; v.y = a.y + c.y; v.z = a.z + c.z; v.w = a.w + c.w;
    }
    __nv_bfloat162 h01 = __floats2bfloat162_rn(v.x, v.y);
    __nv_bfloat162 h23 = __floats2bfloat162_rn(v.z, v.w);
    __nv_bfloat162 l01 = __floats2bfloat162_rn(v.x - __bfloat162float(h01.x),
                                               v.y - __bfloat162float(h01.y));
    __nv_bfloat162 l23 = __floats2bfloat162_rn(v.z - __bfloat162float(h23.x),
                                               v.w - __bfloat162float(h23.y));
    ((__nv_bfloat162*)g_ahi)[idx * 2]     = h01;
    ((__nv_bfloat162*)g_ahi)[idx * 2 + 1] = h23;
    ((__nv_bfloat162*)g_alo)[idx * 2]     = l01;
    ((__nv_bfloat162*)g_alo)[idx * 2 + 1] = l23;
}

// ---------------------------------------------------------------------------
// prepare (leaf): only the embed half (k 256..511); h half replaced by bias fold.
// ---------------------------------------------------------------------------
__global__ void prepare_leaf_kernel(const float* __restrict__ embed) {
    int idx = blockIdx.x * blockDim.x + threadIdx.x;   // M*64 float4s
    if (idx >= MAXM * 64) return;
    int m = idx >> 6, qq = idx & 63;
    int b = m >> 8, n = m & 255;                       // cnt = 256
    int node0 = 511 + 2 * n;
    const float4* e0 = (const float4*)(embed + ((size_t)b * NN + node0) * Xd) + qq;
    const float4* e1 = (const float4*)(embed + ((size_t)b * NN + node0 + 1) * Xd) + qq;
    float4 a = *e0, c = *e1;
    float4 v = make_float4(a.x + c.x, a.y + c.y, a.z + c.z, a.w + c.w);
    __nv_bfloat162 h01 = __floats2bfloat162_rn(v.x, v.y);
    __nv_bfloat162 h23 = __floats2bfloat162_rn(v.z, v.w);
    __nv_bfloat162 l01 = __floats2bfloat162_rn(v.x - __bfloat162float(h01.x),
                                               v.y - __bfloat162float(h01.y));
    __nv_bfloat162 l23 = __floats2bfloat162_rn(v.z - __bfloat162float(h23.x),
                                               v.w - __bfloat162float(h23.y));
    size_t p = (size_t)m * 128 + 64 + qq;              // float4 index within A row
    ((__nv_bfloat162*)g_ahi)[p * 2]     = h01;
    ((__nv_bfloat162*)g_ahi)[p * 2 + 1] = h23;
    ((__nv_bfloat162*)g_alo)[p * 2]     = l01;
    ((__nv_bfloat162*)g_alo)[p * 2 + 1] = l23;
}

// ---------------------------------------------------------------------------
// HMMA GEMM + fused gate epilogue.
// CTA 64 rows x 128 cols, K chunks of 32 from c0..15, cp.async double buffer.
// B fragments come pre-packed (one LDS.128 per (nt,ks) = all 4 B regs).
// ---------------------------------------------------------------------------
__global__ void __launch_bounds__(GT) gemm_hmma_kernel(int cnt, int leaf, int child,
                                                       int parent, int c0) {
    extern __shared__ char sm[];
    const uint32_t sb = smem_to_u32(sm);
    const int tid = threadIdx.x;
    const int wid = tid >> 5, lid = tid & 31;
    const int g = lid >> 2, q = lid & 3;
    const int rowBase = blockIdx.y * 64;
    const int cb = blockIdx.x;                 // colblk: 128 interleaved n

    float acc[16][4];
#pragma unroll
    for (int i = 0; i < 16; i++)
#pragma unroll
        for (int k = 0; k < 4; k++) acc[i][k] = 0.0f;

    const uint4* wsrc = g_wpack + (size_t)cb * (16 * 1024);

#define LOAD_CHUNK(ch, stg) do {                                                  \
    uint32_t sb_ = sb + (stg) * STAGE_BYTES;                                      \
    _Pragma("unroll")                                                             \
    for (int i = tid; i < 512; i += GT) {                                         \
        int part = i >> 8, r = (i >> 2) & 63, s = i & 3;                          \
        uint32_t d = swz_addr(sb_ + (part ? ALO_OFF : AHI_OFF), r, s * 16);       \
        const __nv_bfloat16* srcp = (part ? g_alo : g_ahi)                        \
            + (size_t)(rowBase + r) * KD + (ch) * K_CHUNK + s * 8;                \
        CP_ASYNC16(d, srcp);                                                      \
    }                                                                             \
    _Pragma("unroll")                                                             \
    for (int i = tid; i < 1024; i += GT) {                                        \
        uint32_t d = sb_ + BPK_OFF + (uint32_t)i * 16;                            \
        CP_ASYNC16(d, wsrc + (size_t)(ch) * 1024 + i);                            \
    }                                                                             \
    CP_COMMIT();                                                                  \
} while (0)

    LOAD_CHUNK(c0, c0 & 1);

    for (int ch = c0; ch < 16; ch++) {
        int stg = ch & 1;
        if (ch + 1 < 16) {
            LOAD_CHUNK(ch + 1, stg ^ 1);
            CP_WAIT(1);
        } else {
            CP_WAIT(0);
        }
        __syncthreads();

        uint32_t st = sb + stg * STAGE_BYTES;
        const int rowA = wid * 16 + g;
#pragma unroll
        for (int ks = 0; ks < 2; ks++) {
            int kb = ks * 32 + q * 4;
            uint32_t ah0 = lds_u32(swz_addr(st + AHI_OFF, rowA,     kb));
            uint32_t ah1 = lds_u32(swz_addr(st + AHI_OFF, rowA + 8, kb));
            uint32_t ah2 = lds_u32(swz_addr(st + AHI_OFF, rowA,     kb + 16));
            uint32_t ah3 = lds_u32(swz_addr(st + AHI_OFF, rowA + 8, kb + 16));
            uint32_t al0 = lds_u32(swz_addr(st + ALO_OFF, rowA,     kb));
            uint32_t al1 = lds_u32(swz_addr(st + ALO_OFF, rowA + 8, kb));
            uint32_t al2 = lds_u32(swz_addr(st + ALO_OFF, rowA,     kb + 16));
            uint32_t al3 = lds_u32(swz_addr(st + ALO_OFF, rowA + 8, kb + 16));
            uint32_t bbase = st + BPK_OFF + (uint32_t)ks * 8192 + (uint32_t)lid * 16;
#pragma unroll
            for (int nt = 0; nt < 16; nt++) {
                uint4 bb = lds_u128(bbase + (uint32_t)nt * 512);
                MMA_BF16(acc[nt], ah0, ah1, ah2, ah3, bb.x, bb.y);
                MMA_BF16(acc[nt], ah0, ah1, ah2, ah3, bb.z, bb.w);
                MMA_BF16(acc[nt], al0, al1, al2, al3, bb.x, bb.y);
            }
        }
        __syncthreads();
    }
#undef LOAD_CHUNK

    // Fused gate epilogue (same fragment/shuffle mapping as R3).
    const bool evenq = ((q & 1) == 0);
    const int m = rowBase + wid * 16 + g + ((lid & 1) ? 8 : 0);
    const int b = m / cnt, n = m - b * cnt;
    const float* crow = g_c[child] + (size_t)(b * 2 * cnt + 2 * n) * Hd;
    const float* bp = leaf ? g_biasleaf : g_bias;
    float* hp = g_h[parent] + (size_t)m * Hd;
    float* cp = g_c[parent] + (size_t)m * Hd;
    const int jb = cb * 32 + (q >> 1);
#pragma unroll
    for (int nt = 0; nt < 16; nt++) {
        float t0 = __shfl_xor_sync(0xffffffffu, acc[nt][0], 1);
        float t1 = __shfl_xor_sync(0xffffffffu, acc[nt][1], 1);
        float t2 = __shfl_xor_sync(0xffffffffu, acc[nt][2], 1);
        float t3 = __shfl_xor_sync(0xffffffffu, acc[nt][3], 1);
        float pf = evenq ? acc[nt][0] : t2;
        float pi = evenq ? acc[nt][1] : t3;
        float pu = evenq ? t0 : acc[nt][2];
        float po = evenq ? t1 : acc[nt][3];
        int j = jb + nt * 2;
        float f  = sigmoidf_(pf + bp[j]);
        float ig = sigmoidf_(pi + bp[256 + j]);
        float u  = tanhf    (pu + bp[512 + j]);
        float o  = sigmoidf_(po + bp[768 + j]);
        float csum = leaf ? 2.0f * g_leaf_c[j] : (crow[j] + crow[Hd + j]);
        float cn = ig * u + f * csum;
        cp[j] = cn;
        hp[j] = o * tanhf(cn);
    }
}

// ---------------------------------------------------------------------------
// Head MLP (tiny, fp32): out = act(A @ W^T + bias [+ g_y])
// ---------------------------------------------------------------------------
__global__ void head_kernel(const float* __restrict__ W, const float* __restrict__ bias,
                            int src, int dst, int addy, int act, float* __restrict__ out) {
    __shared__ float arow[256];
    int b = blockIdx.x;
    int j = threadIdx.x;
    const float* A = (src == 0) ? g_h[1] : (src == 1) ? g_t : g_z;
    arow[j] = A[b * 256 + j];
    __syncthreads();
    float acc = bias[j];
    const float* wr = W + j * 256;
#pragma unroll 8
    for (int k = 0; k < 256; k++) acc += arow[k] * wr[k];
    if (addy) acc += g_y[b * 256 + j];
    if (act == 1) acc = tanhf(acc);
    else if (act == 2) acc = fmaxf(acc, 0.0f);
    float* O = (dst == 0) ? g_y : (dst == 1) ? g_t : (dst == 2) ? g_z : out;
    O[b * 256 + j] = acc;
}

// ---------------------------------------------------------------------------
extern "C" void kernel_launch(void* const* d_in, const int* in_sizes, int n_in,
                              void* d_out, int out_size) {
    const float* embed = (const float*)d_in[0];
    const float* Wf  = (const float*)d_in[1];
    const float* bf  = (const float*)d_in[2];
    const float* b_f = (const float*)d_in[3];
    const float* Wi  = (const float*)d_in[4];
    const float* bi  = (const float*)d_in[5];
    const float* b_i = (const float*)d_in[6];
    const float* Wu  = (const float*)d_in[7];
    const float* bu  = (const float*)d_in[8];
    const float* b_u = (const float*)d_in[9];
    const float* Wo  = (const float*)d_in[10];
    const float* bo  = (const float*)d_in[11];
    const float* b_o = (const float*)d_in[12];
    const float* W1  = (const float*)d_in[13];
    const float* bl1 = (const float*)d_in[14];
    const float* W2  = (const float*)d_in[15];
    const float* bl2 = (const float*)d_in[16];
    const float* W3  = (const float*)d_in[17];
    const float* bl3 = (const float*)d_in[18];
    const float* W4  = (const float*)d_in[19];
    const float* bl4 = (const float*)d_in[20];
    float* out = (float*)d_out;

    cudaFuncSetAttribute(gemm_hmma_kernel, cudaFuncAttributeMaxDynamicSharedMemorySize, SMEM_SZ);

    leaf_bias_kernel<<<1, 256>>>(bf, b_f, bi, b_i, bu, b_u, bo, b_o);
    leafdot_kernel<<<4, 256>>>(Wf, Wi, Wu, Wo);
    convert_w_kernel<<<512, 256>>>(Wf, Wi, Wu, Wo);

    int pp = 0;
    for (int l = 8; l >= 0; --l) {
        int cnt = 1 << l;
        int M = Bdim * cnt;
        int leaf = (l == 8);
        int child = pp, parent = pp ^ 1;
        if (leaf)
            prepare_leaf_kernel<<<(MAXM * 64 + 255) / 256, 256>>>(embed);
        else
            prepare_kernel<<<(M * 128 + 255) / 256, 256>>>(embed, cnt, child);
        gemm_hmma_kernel<<<dim3(8, M / 64), GT, SMEM_SZ>>>(cnt, leaf, child, parent, leaf ? 8 : 0);
        pp = parent;
    }
    // pp == 1: root hidden state in g_h[1][0 : 128*256]

    head_kernel<<<128, 256>>>(W1, bl1, 0, 0, 0, 1, out);  // y  = tanh(hr @ W1^T + bl1)
    head_kernel<<<128, 256>>>(W2, bl2, 0, 1, 0, 2, out);  // t  = relu(hr @ W2^T + bl2)
    head_kernel<<<128, 256>>>(W3, bl3, 1, 2, 1, 0, out);  // z  = t @ W3^T + bl3 + y
    head_kernel<<<128, 256>>>(W4, bl4, 2, 3, 0, 2, out);  // out = relu(z @ W4^T + bl4)
}

// round 5
// speedup vs baseline: 3.9671x; 1.3891x over previous
#include <cuda_runtime.h>
#include <cuda_fp16.h>
#include <math.h>
#include <stdint.h>

// Problem constants
#define Bdim 128
#define NN   1023
#define Xd   256
#define Hd   256
#define KD   512     // H + X
#define GD   1024    // 4 gates * H
#define MAXCNT 256
#define MAXM   (Bdim*MAXCNT)   // 32768

// ---------------------------------------------------------------------------
// Static device scratch (allocation-free rule)
// ---------------------------------------------------------------------------
__device__ float g_h[2][MAXM*Hd];            // ping-pong hidden states
__device__ float g_c[2][MAXM*Hd];            // ping-pong cell states
__device__ __half g_ah[MAXM*KD];             // A (h_sum) fp16
// W packed in mma-fragment order: [colblk 8][chunk 16][ks 2][ntp 8][lane 32]
// uint4 = {nt0.b0, nt0.b1, nt1.b0, nt1.b1} (fp16x2 each) for two n-tiles.
__device__ uint4 g_wpack[8*16*2*8*32];       // 65536 * 16B = 1 MB
__device__ float g_leaf_h[Hd];
__device__ float g_leaf_c[Hd];
__device__ float g_bias[GD];                 // gate-major: [f i u o] x 256
__device__ float g_biasleaf[GD];             // g_bias + leaf-h constant dot
__device__ float g_y[Bdim*Hd];
__device__ float g_t[Bdim*Hd];
__device__ float g_z[Bdim*Hd];

__device__ __forceinline__ float sigmoidf_(float x) { return 1.0f / (1.0f + expf(-x)); }

__device__ __forceinline__ uint32_t smem_to_u32(const void* p) {
    uint32_t a;
    asm("{ .reg .u64 t; cvta.to.shared.u64 t, %1; cvt.u32.u64 %0, t; }" : "=r"(a) : "l"(p));
    return a;
}
__device__ __forceinline__ uint32_t lds_u32(uint32_t addr) {
    uint32_t v;
    asm volatile("ld.shared.b32 %0, [%1];" : "=r"(v) : "r"(addr));
    return v;
}
__device__ __forceinline__ uint4 lds_u128(uint32_t addr) {
    uint4 v;
    asm volatile("ld.shared.v4.b32 {%0,%1,%2,%3}, [%4];"
                 : "=r"(v.x), "=r"(v.y), "=r"(v.z), "=r"(v.w) : "r"(addr));
    return v;
}
#define CP_ASYNC16(daddr, src) \
    asm volatile("cp.async.cg.shared.global [%0], [%1], 16;" :: "r"(daddr), "l"(src) : "memory")
#define CP_COMMIT() asm volatile("cp.async.commit_group;" ::: "memory")
#define CP_WAIT(n)  asm volatile("cp.async.wait_group %0;" :: "n"(n) : "memory")

#define MMA_F16(d, a0, a1, a2, a3, b0, b1) \
    asm volatile("mma.sync.aligned.m16n8k16.row.col.f32.f16.f16.f32 " \
        "{%0,%1,%2,%3}, {%4,%5,%6,%7}, {%8,%9}, {%0,%1,%2,%3};" \
        : "+f"((d)[0]), "+f"((d)[1]), "+f"((d)[2]), "+f"((d)[3]) \
        : "r"(a0), "r"(a1), "r"(a2), "r"(a3), "r"(b0), "r"(b1))

// GEMM geometry: CTA = 64 rows x 128 interleaved cols, 128 threads (4 warps)
#define GT 128
#define K_CHUNK 32
// smem stage layout
#define A_OFF   0                 // 64 rows * 64B = 4096
#define BPK_OFF 4096              // packed B: 2ks*8ntp*32lane*16B = 8192
#define STAGE_BYTES 12288
#define SMEM_SZ (2 * STAGE_BYTES) // 24576

// phys addr of byte kb (0..63) within swizzled 64B A row
__device__ __forceinline__ uint32_t swz_addr(uint32_t base, int row, int kb) {
    return base + row * 64 + (((((uint32_t)kb >> 4) ^ ((uint32_t)row >> 1)) & 3u) << 4) + (kb & 15);
}

__device__ __forceinline__ uint32_t pk_h2(float a, float b) {
    __half2 t = __floats2half2_rn(a, b);
    return *reinterpret_cast<uint32_t*>(&t);
}

// ---------------------------------------------------------------------------
// Setup: leaf vectors + gate-major combined bias
// ---------------------------------------------------------------------------
__global__ void leaf_bias_kernel(const float* __restrict__ bf, const float* __restrict__ b_f,
                                 const float* __restrict__ bi, const float* __restrict__ b_i,
                                 const float* __restrict__ bu, const float* __restrict__ b_u,
                                 const float* __restrict__ bo, const float* __restrict__ b_o) {
    int j = threadIdx.x;
    float ig = sigmoidf_(bi[j] + b_i[j]);
    float ug = tanhf(bu[j] + b_u[j]);
    float cl = ig * ug;
    g_leaf_c[j] = cl;
    g_leaf_h[j] = sigmoidf_(bo[j] + b_o[j]) * tanhf(cl);
    g_bias[j]       = bf[j] + b_f[j];
    g_bias[256 + j] = bi[j] + b_i[j];
    g_bias[512 + j] = bu[j] + b_u[j];
    g_bias[768 + j] = bo[j] + b_o[j];
}

// ---------------------------------------------------------------------------
// Leaf bias fold: g_biasleaf = g_bias + sum_{k<256} 2*leaf_h[k]*W[j][k] (fp32 exact)
// ---------------------------------------------------------------------------
__global__ void leafdot_kernel(const float* __restrict__ Wf, const float* __restrict__ Wi,
                               const float* __restrict__ Wu, const float* __restrict__ Wo) {
    __shared__ float lh[256];
    int t = threadIdx.x;
    lh[t] = 2.0f * g_leaf_h[t];
    __syncthreads();
    int n = blockIdx.x * 256 + t;     // 0..1023
    int j = n >> 2, gate = n & 3;
    const float* W = (gate == 0) ? Wf : (gate == 1) ? Wi : (gate == 2) ? Wu : Wo;
    const float* wr = W + (size_t)j * 512;
    float acc = 0.0f;
#pragma unroll 8
    for (int k = 0; k < 256; k++) acc += wr[k] * lh[k];
    g_biasleaf[gate * 256 + j] = g_bias[gate * 256 + j] + acc;
}

// ---------------------------------------------------------------------------
// Weight conversion into packed fp16 fragment order (one-time).
// idx -> [cb 8][ch 16][ks 2][ntp 8][lane 32]
// ---------------------------------------------------------------------------
__global__ void convert_w_kernel(const float* __restrict__ Wf, const float* __restrict__ Wi,
                                 const float* __restrict__ Wu, const float* __restrict__ Wo) {
    int idx = blockIdx.x * 256 + threadIdx.x;   // 0 .. 65535
    int lane = idx & 31;
    int ntp  = (idx >> 5) & 7;
    int ks   = (idx >> 8) & 1;
    int ch   = (idx >> 9) & 15;
    int cb   = idx >> 13;
    int tig = lane & 3;
    int k0 = ch * 32 + ks * 16 + tig * 2;
    uint4 v;
    uint32_t* vv = (uint32_t*)&v;
#pragma unroll
    for (int half = 0; half < 2; half++) {
        int nt = ntp * 2 + half;
        int n = cb * 128 + nt * 8 + (lane >> 2);    // interleaved n = j*4+gate
        int j = n >> 2, gate = n & 3;
        const float* W = (gate == 0) ? Wf : (gate == 1) ? Wi : (gate == 2) ? Wu : Wo;
        const float* wr = W + (size_t)j * 512;
        vv[half * 2]     = pk_h2(wr[k0],     wr[k0 + 1]);   // b0
        vv[half * 2 + 1] = pk_h2(wr[k0 + 8], wr[k0 + 9]);   // b1
    }
    g_wpack[idx] = v;
}

// ---------------------------------------------------------------------------
// prepare (non-leaf): A[m,:] = [h_c0+h_c1 | e_c0+e_c1] as fp16
// ---------------------------------------------------------------------------
__global__ void prepare_kernel(const float* __restrict__ embed, int cnt, int child) {
    int idx = blockIdx.x * blockDim.x + threadIdx.x;
    int M = Bdim * cnt;
    if (idx >= M * 128) return;
    int m = idx >> 7, q = idx & 127;
    int b = m / cnt, n = m - b * cnt;
    float4 v;
    if (q < 64) {
        const float4* hc = (const float4*)(g_h[child] + (size_t)(b * 2 * cnt + 2 * n) * Hd) + q;
        float4 a = hc[0];
        float4 c = hc[Hd / 4];
        v.x = a.x + c.x; v.y = a.y + c.y; v.z = a.z + c.z; v.w = a.w + c.w;
    } else {
        int node0 = 2 * cnt - 1 + 2 * n;
        const float4* e0 = (const float4*)(embed + ((size_t)b * NN + node0) * Xd) + (q - 64);
        const float4* e1 = (const float4*)(embed + ((size_t)b * NN + node0 + 1) * Xd) + (q - 64);
        float4 a = *e0, c = *e1;
        v.x = a.x + c.x; v.y = a.y + c.y; v.z = a.z + c.z; v.w = a.w + c.w;
    }
    ((__half2*)g_ah)[idx * 2]     = __floats2half2_rn(v.x, v.y);
    ((__half2*)g_ah)[idx * 2 + 1] = __floats2half2_rn(v.z, v.w);
}

// ---------------------------------------------------------------------------
// prepare (leaf): only the embed half (k 256..511)
// ---------------------------------------------------------------------------
__global__ void prepare_leaf_kernel(const float* __restrict__ embed) {
    int idx = blockIdx.x * blockDim.x + threadIdx.x;   // M*64 float4s
    if (idx >= MAXM * 64) return;
    int m = idx >> 6, qq = idx & 63;
    int b = m >> 8, n = m & 255;                       // cnt = 256
    int node0 = 511 + 2 * n;
    const float4* e0 = (const float4*)(embed + ((size_t)b * NN + node0) * Xd) + qq;
    const float4* e1 = (const float4*)(embed + ((size_t)b * NN + node0 + 1) * Xd) + qq;
    float4 a = *e0, c = *e1;
    size_t p = (size_t)m * 256 + 128 + (size_t)qq * 2;  // half2 index
    ((__half2*)g_ah)[p]     = __floats2half2_rn(a.x + c.x, a.y + c.y);
    ((__half2*)g_ah)[p + 1] = __floats2half2_rn(a.z + c.z, a.w + c.w);
}

// ---------------------------------------------------------------------------
// HMMA GEMM + fused gate epilogue (single fp16 MMA per tile).
// CTA 64 rows x 128 cols, K chunks of 32 (c0..15), cp.async double buffer.
// ---------------------------------------------------------------------------
__global__ void __launch_bounds__(GT) gemm_hmma_kernel(int cnt, int leaf, int child,
                                                       int parent, int c0) {
    extern __shared__ char sm[];
    const uint32_t sb = smem_to_u32(sm);
    const int tid = threadIdx.x;
    const int wid = tid >> 5, lid = tid & 31;
    const int g = lid >> 2, q = lid & 3;
    const int rowBase = blockIdx.y * 64;
    const int cb = blockIdx.x;                 // colblk: 128 interleaved n

    float acc[16][4];
#pragma unroll
    for (int i = 0; i < 16; i++)
#pragma unroll
        for (int k = 0; k < 4; k++) acc[i][k] = 0.0f;

    const uint4* wsrc = g_wpack + (size_t)cb * (16 * 512);

#define LOAD_CHUNK(ch, stg) do {                                                  \
    uint32_t sb_ = sb + (stg) * STAGE_BYTES;                                      \
    _Pragma("unroll")                                                             \
    for (int i = tid; i < 256; i += GT) {                                         \
        int r = i >> 2, s = i & 3;                                                \
        uint32_t d = swz_addr(sb_ + A_OFF, r, s * 16);                            \
        const __half* srcp = g_ah + (size_t)(rowBase + r) * KD + (ch) * K_CHUNK + s * 8; \
        CP_ASYNC16(d, srcp);                                                      \
    }                                                                             \
    _Pragma("unroll")                                                             \
    for (int i = tid; i < 512; i += GT) {                                         \
        uint32_t d = sb_ + BPK_OFF + (uint32_t)i * 16;                            \
        CP_ASYNC16(d, wsrc + (size_t)(ch) * 512 + i);                             \
    }                                                                             \
    CP_COMMIT();                                                                  \
} while (0)

    LOAD_CHUNK(c0, c0 & 1);

    for (int ch = c0; ch < 16; ch++) {
        int stg = ch & 1;
        if (ch + 1 < 16) {
            LOAD_CHUNK(ch + 1, stg ^ 1);
            CP_WAIT(1);
        } else {
            CP_WAIT(0);
        }
        __syncthreads();

        uint32_t st = sb + stg * STAGE_BYTES;
        const int rowA = wid * 16 + g;
#pragma unroll
        for (int ks = 0; ks < 2; ks++) {
            int kb = ks * 32 + q * 4;
            uint32_t a0 = lds_u32(swz_addr(st + A_OFF, rowA,     kb));
            uint32_t a1 = lds_u32(swz_addr(st + A_OFF, rowA + 8, kb));
            uint32_t a2 = lds_u32(swz_addr(st + A_OFF, rowA,     kb + 16));
            uint32_t a3 = lds_u32(swz_addr(st + A_OFF, rowA + 8, kb + 16));
            uint32_t bbase = st + BPK_OFF + (uint32_t)ks * 4096 + (uint32_t)lid * 16;
#pragma unroll
            for (int ntp = 0; ntp < 8; ntp++) {
                uint4 bb = lds_u128(bbase + (uint32_t)ntp * 512);
                MMA_F16(acc[ntp * 2],     a0, a1, a2, a3, bb.x, bb.y);
                MMA_F16(acc[ntp * 2 + 1], a0, a1, a2, a3, bb.z, bb.w);
            }
        }
        __syncthreads();
    }
#undef LOAD_CHUNK

    // Fused gate epilogue (fragment/shuffle mapping as before).
    const bool evenq = ((q & 1) == 0);
    const int m = rowBase + wid * 16 + g + ((lid & 1) ? 8 : 0);
    const int b = m / cnt, n = m - b * cnt;
    const float* crow = g_c[child] + (size_t)(b * 2 * cnt + 2 * n) * Hd;
    const float* bp = leaf ? g_biasleaf : g_bias;
    float* hp = g_h[parent] + (size_t)m * Hd;
    float* cp = g_c[parent] + (size_t)m * Hd;
    const int jb = cb * 32 + (q >> 1);
#pragma unroll
    for (int nt = 0; nt < 16; nt++) {
        float t0 = __shfl_xor_sync(0xffffffffu, acc[nt][0], 1);
        float t1 = __shfl_xor_sync(0xffffffffu, acc[nt][1], 1);
        float t2 = __shfl_xor_sync(0xffffffffu, acc[nt][2], 1);
        float t3 = __shfl_xor_sync(0xffffffffu, acc[nt][3], 1);
        float pf = evenq ? acc[nt][0] : t2;
        float pi = evenq ? acc[nt][1] : t3;
        float pu = evenq ? t0 : acc[nt][2];
        float po = evenq ? t1 : acc[nt][3];
        int j = jb + nt * 2;
        float f  = sigmoidf_(pf + bp[j]);
        float ig = sigmoidf_(pi + bp[256 + j]);
        float u  = tanhf    (pu + bp[512 + j]);
        float o  = sigmoidf_(po + bp[768 + j]);
        float csum = leaf ? 2.0f * g_leaf_c[j] : (crow[j] + crow[Hd + j]);
        float cn = ig * u + f * csum;
        cp[j] = cn;
        hp[j] = o * tanhf(cn);
    }
}

// ---------------------------------------------------------------------------
// Head MLP (tiny, fp32): out = act(A @ W^T + bias [+ g_y])
// ---------------------------------------------------------------------------
__global__ void head_kernel(const float* __restrict__ W, const float* __restrict__ bias,
                            int src, int dst, int addy, int act, float* __restrict__ out) {
    __shared__ float arow[256];
    int b = blockIdx.x;
    int j = threadIdx.x;
    const float* A = (src == 0) ? g_h[1] : (src == 1) ? g_t : g_z;
    arow[j] = A[b * 256 + j];
    __syncthreads();
    float acc = bias[j];
    const float* wr = W + j * 256;
#pragma unroll 8
    for (int k = 0; k < 256; k++) acc += arow[k] * wr[k];
    if (addy) acc += g_y[b * 256 + j];
    if (act == 1) acc = tanhf(acc);
    else if (act == 2) acc = fmaxf(acc, 0.0f);
    float* O = (dst == 0) ? g_y : (dst == 1) ? g_t : (dst == 2) ? g_z : out;
    O[b * 256 + j] = acc;
}

// ---------------------------------------------------------------------------
extern "C" void kernel_launch(void* const* d_in, const int* in_sizes, int n_in,
                              void* d_out, int out_size) {
    const float* embed = (const float*)d_in[0];
    const float* Wf  = (const float*)d_in[1];
    const float* bf  = (const float*)d_in[2];
    const float* b_f = (const float*)d_in[3];
    const float* Wi  = (const float*)d_in[4];
    const float* bi  = (const float*)d_in[5];
    const float* b_i = (const float*)d_in[6];
    const float* Wu  = (const float*)d_in[7];
    const float* bu  = (const float*)d_in[8];
    const float* b_u = (const float*)d_in[9];
    const float* Wo  = (const float*)d_in[10];
    const float* bo  = (const float*)d_in[11];
    const float* b_o = (const float*)d_in[12];
    const float* W1  = (const float*)d_in[13];
    const float* bl1 = (const float*)d_in[14];
    const float* W2  = (const float*)d_in[15];
    const float* bl2 = (const float*)d_in[16];
    const float* W3  = (const float*)d_in[17];
    const float* bl3 = (const float*)d_in[18];
    const float* W4  = (const float*)d_in[19];
    const float* bl4 = (const float*)d_in[20];
    float* out = (float*)d_out;

    cudaFuncSetAttribute(gemm_hmma_kernel, cudaFuncAttributeMaxDynamicSharedMemorySize, SMEM_SZ);

    leaf_bias_kernel<<<1, 256>>>(bf, b_f, bi, b_i, bu, b_u, bo, b_o);
    leafdot_kernel<<<4, 256>>>(Wf, Wi, Wu, Wo);
    convert_w_kernel<<<256, 256>>>(Wf, Wi, Wu, Wo);

    int pp = 0;
    for (int l = 8; l >= 0; --l) {
        int cnt = 1 << l;
        int M = Bdim * cnt;
        int leaf = (l == 8);
        int child = pp, parent = pp ^ 1;
        if (leaf)
            prepare_leaf_kernel<<<(MAXM * 64 + 255) / 256, 256>>>(embed);
        else
            prepare_kernel<<<(M * 128 + 255) / 256, 256>>>(embed, cnt, child);
        gemm_hmma_kernel<<<dim3(8, M / 64), GT, SMEM_SZ>>>(cnt, leaf, child, parent, leaf ? 8 : 0);
        pp = parent;
    }
    // pp == 1: root hidden state in g_h[1][0 : 128*256]

    head_kernel<<<128, 256>>>(W1, bl1, 0, 0, 0, 1, out);  // y  = tanh(hr @ W1^T + bl1)
    head_kernel<<<128, 256>>>(W2, bl2, 0, 1, 0, 2, out);  // t  = relu(hr @ W2^T + bl2)
    head_kernel<<<128, 256>>>(W3, bl3, 1, 2, 1, 0, out);  // z  = t @ W3^T + bl3 + y
    head_kernel<<<128, 256>>>(W4, bl4, 2, 3, 0, 2, out);  // out = relu(z @ W4^T + bl4)
}